// round 15
// baseline (speedup 1.0000x reference)
#include <cuda_runtime.h>

#define BATCH 50000
#define K 10
#define DIM 128
#define VECS_PER_ROW (DIM / 4)   // 32 float4 per row — one per lane

// fp32 one-pass gather-mean. The timed harness replays a captured graph, so
// cross-replay L2 state matters: the 51.2MB feature table must stay resident
// while the 25.6MB write-once output must not allocate L2 lines at all.
// __stcs (evict-first, still allocates) already bought 21.2 -> 18.9us;
// __stwt (write-through, no L2 allocation) is the strict version.
__global__ __launch_bounds__(256) void mean_agg_kernel(
    const int* __restrict__ nodes,        // [BATCH]
    const int* __restrict__ neighbours,   // [BATCH, K]
    const float4* __restrict__ features,  // [N_NODES, 32] as float4
    float4* __restrict__ out)             // [BATCH, 32] as float4
{
    const int warp = (blockIdx.x * blockDim.x + threadIdx.x) >> 5;
    const int lane = threadIdx.x & 31;
    if (warp >= BATCH) return;

    // 11 row ids (self + K neighbours); uniform across the warp -> broadcast.
    int idx[K + 1];
    idx[0] = __ldg(&nodes[warp]);
#pragma unroll
    for (int k = 0; k < K; k++) idx[k + 1] = __ldg(&neighbours[warp * K + k]);

    // 11 gathered float4 loads; each warp request = 4 x 128B lines — the
    // request shape that reaches the LTS sector cap.
    float4 v[K + 1];
#pragma unroll
    for (int k = 0; k < K + 1; k++) {
        v[k] = __ldg(&features[(long long)idx[k] * VECS_PER_ROW + lane]);
    }

    float4 acc = v[0];
#pragma unroll
    for (int k = 1; k < K + 1; k++) {
        acc.x += v[k].x;
        acc.y += v[k].y;
        acc.z += v[k].z;
        acc.w += v[k].w;
    }

    const float s = 1.0f / (float)(K + 1);
    acc.x *= s; acc.y *= s; acc.z *= s; acc.w *= s;

    // Write-through store: zero L2 footprint for the write-once output.
    __stwt(&out[(long long)warp * VECS_PER_ROW + lane], acc);
}

extern "C" void kernel_launch(void* const* d_in, const int* in_sizes, int n_in,
                              void* d_out, int out_size)
{
    const int*    nodes      = (const int*)d_in[0];
    const int*    neighbours = (const int*)d_in[1];
    const float4* features   = (const float4*)d_in[2];
    float4*       out        = (float4*)d_out;

    // One warp per row, 8 warps per 256-thread block.
    const int warps_per_block = 256 / 32;
    const int blocks = (BATCH + warps_per_block - 1) / warps_per_block;
    mean_agg_kernel<<<blocks, 256>>>(nodes, neighbours, features, out);
}

// round 16
// speedup vs baseline: 1.1218x; 1.1218x over previous
#include <cuda_runtime.h>

#define BATCH 50000
#define K 10
#define DIM 128
#define VECS_PER_ROW (DIM / 4)   // 32 float4 per row — one per lane

// FINAL (proven 18.9us): fp32 one-pass gather-mean at the B300 LTS sector cap,
// with evict-first output stores.
//
// Measured policy ladder for the write-once 25.6MB output (timed graph loop):
//   default store -> 21.2us  (output allocates L2, evicts the 51.2MB feature
//                             table between replays -> gather DRAM-miss tax)
//   __stwt        -> 21.2us  (no allocation, but synchronous write-through
//                             burns DRAM/LTS bandwidth during the kernel)
//   __stcs        -> 18.9us  (allocates evict-first: buffers the write burst,
//                             protects the features, lazy full-line writeback)
//
// Gather: one warp per output row, lane owns one float4; 11 gathered
// 512B-row requests (4 x 128B lines each) — the request shape measured to
// reach the chip LTS ceiling (~15 TB/s delivered in the timed loop).
__global__ __launch_bounds__(256) void mean_agg_kernel(
    const int* __restrict__ nodes,        // [BATCH]
    const int* __restrict__ neighbours,   // [BATCH, K]
    const float4* __restrict__ features,  // [N_NODES, 32] as float4
    float4* __restrict__ out)             // [BATCH, 32] as float4
{
    const int warp = (blockIdx.x * blockDim.x + threadIdx.x) >> 5;
    const int lane = threadIdx.x & 31;
    if (warp >= BATCH) return;

    // 11 row ids (self + K neighbours); uniform across the warp -> broadcast.
    int idx[K + 1];
    idx[0] = __ldg(&nodes[warp]);
#pragma unroll
    for (int k = 0; k < K; k++) idx[k + 1] = __ldg(&neighbours[warp * K + k]);

    float4 v[K + 1];
#pragma unroll
    for (int k = 0; k < K + 1; k++) {
        v[k] = __ldg(&features[(long long)idx[k] * VECS_PER_ROW + lane]);
    }

    float4 acc = v[0];
#pragma unroll
    for (int k = 1; k < K + 1; k++) {
        acc.x += v[k].x;
        acc.y += v[k].y;
        acc.z += v[k].z;
        acc.w += v[k].w;
    }

    const float s = 1.0f / (float)(K + 1);
    acc.x *= s; acc.y *= s; acc.z *= s; acc.w *= s;

    // Evict-first store: protects feature-table L2 residency across replays.
    __stcs(&out[(long long)warp * VECS_PER_ROW + lane], acc);
}

extern "C" void kernel_launch(void* const* d_in, const int* in_sizes, int n_in,
                              void* d_out, int out_size)
{
    const int*    nodes      = (const int*)d_in[0];
    const int*    neighbours = (const int*)d_in[1];
    const float4* features   = (const float4*)d_in[2];
    float4*       out        = (float4*)d_out;

    // One warp per row, 8 warps per 256-thread block.
    const int warps_per_block = 256 / 32;
    const int blocks = (BATCH + warps_per_block - 1) / warps_per_block;
    mean_agg_kernel<<<blocks, 256>>>(nodes, neighbours, features, out);
}